// round 15
// baseline (speedup 1.0000x reference)
#include <cuda_runtime.h>
#include <cstdint>

#define BROWS  32768
#define KROWS  8192
#define DDIM   256
#define QSCALE 26.0f
#define TH_INT 2200
#define CAP    256
#define CLCAP  64

// ---------------- device globals (no cudaMalloc allowed) --------------------
__device__ __align__(16) int8_t g_z8[BROWS * DDIM];    // round(-26 * z)
__device__ __align__(16) int8_t g_cb8[KROWS * DDIM];   // round( 26 * e)
__device__ __align__(16) float  g_esq[KROWS];          // 0.5*||e||^2 exact
__device__ __align__(16) int    g_esq676[KROWS];       // round(676 * esq)
__device__ int   g_row_idx[BROWS];
__device__ int   g_ccnt[BROWS];
__device__ int   g_cand[BROWS * CAP];                  // 32 MB
__device__ int   g_nclamp;
__device__ int   g_clampidx[CLCAP];
__device__ float g_partial[BROWS / 64];

// ---------------- asm helpers (baseline PTX only) ----------------------------
__device__ __forceinline__ uint32_t smem_u32(const void* p) {
    uint32_t a;
    asm("{ .reg .u64 t; cvta.to.shared.u64 t, %1; cvt.u32.u64 %0, t; }"
        : "=r"(a) : "l"(p));
    return a;
}
__device__ __forceinline__ void ldmx4(uint32_t r[4], uint32_t addr) {
    asm volatile("ldmatrix.sync.aligned.m8n8.x4.shared.b16 {%0,%1,%2,%3}, [%4];\n"
        : "=r"(r[0]), "=r"(r[1]), "=r"(r[2]), "=r"(r[3]) : "r"(addr));
}
// int8 MMA: m16n8k32, s32 accumulate. Fragments byte-identical to f16 m16n8k16.
__device__ __forceinline__ void imma16832(int c[4], const uint32_t a[4],
                                          uint32_t b0, uint32_t b1) {
    asm volatile(
        "mma.sync.aligned.m16n8k32.row.col.s32.s8.s8.s32 "
        "{%0,%1,%2,%3}, {%4,%5,%6,%7}, {%8,%9}, {%0,%1,%2,%3};\n"
        : "+r"(c[0]), "+r"(c[1]), "+r"(c[2]), "+r"(c[3])
        : "r"(a[0]), "r"(a[1]), "r"(a[2]), "r"(a[3]), "r"(b0), "r"(b1));
}
__device__ __forceinline__ void cp16(uint32_t dst, const void* src) {
    asm volatile("cp.async.cg.shared.global [%0], [%1], 16;\n"
        :: "r"(dst), "l"(src));
}
#define CPC()  asm volatile("cp.async.commit_group;\n" ::: "memory")
#define CPW(n) asm volatile("cp.async.wait_group %0;\n" :: "n"(n) : "memory")

// ---------------- prep: esq, esq676, counter resets ---------------------------
__global__ void prep_kernel(const float* __restrict__ cb) {
    int gtid = blockIdx.x * 256 + threadIdx.x;
    if (gtid < BROWS) g_ccnt[gtid] = 0;
    if (gtid == 0) g_nclamp = 0;
    int row = blockIdx.x * 8 + (threadIdx.x >> 5);
    if (row >= KROWS) return;
    int lane = threadIdx.x & 31;
    const float4* p = reinterpret_cast<const float4*>(cb + (size_t)row * DDIM);
    float s = 0.f;
#pragma unroll
    for (int i = 0; i < 2; i++) {
        float4 v = p[lane + 32 * i];
        s += v.x * v.x + v.y * v.y + v.z * v.z + v.w * v.w;
    }
#pragma unroll
    for (int o = 16; o; o >>= 1) s += __shfl_down_sync(0xffffffffu, s, o);
    if (lane == 0) {
        float e = 0.5f * s;
        g_esq[row] = e;
        g_esq676[row] = __float2int_rn(676.0f * e);
    }
}

// ---------------- quantizers -------------------------------------------------
__global__ void quant_z(const float* __restrict__ src) {
    int i = blockIdx.x * 256 + threadIdx.x;
    if (i >= BROWS * DDIM / 4) return;
    float4 v = reinterpret_cast<const float4*>(src)[i];
    int q0 = __float2int_rn(-QSCALE * v.x);
    int q1 = __float2int_rn(-QSCALE * v.y);
    int q2 = __float2int_rn(-QSCALE * v.z);
    int q3 = __float2int_rn(-QSCALE * v.w);
    bool bad = (q0 > 127 || q0 < -127 || q1 > 127 || q1 < -127 ||
                q2 > 127 || q2 < -127 || q3 > 127 || q3 < -127);
    if (bad) {
        q0 = max(-127, min(127, q0)); q1 = max(-127, min(127, q1));
        q2 = max(-127, min(127, q2)); q3 = max(-127, min(127, q3));
        g_ccnt[i >> 6] = 0x40000000;   // sentinel: force exact full scan
    }
    char4 c; c.x = (char)q0; c.y = (char)q1; c.z = (char)q2; c.w = (char)q3;
    *reinterpret_cast<char4*>(g_z8 + (size_t)i * 4) = c;
}

__global__ void quant_cb(const float* __restrict__ src) {
    int i = blockIdx.x * 256 + threadIdx.x;
    if (i >= KROWS * DDIM / 4) return;
    float4 v = reinterpret_cast<const float4*>(src)[i];
    int q0 = __float2int_rn(QSCALE * v.x);
    int q1 = __float2int_rn(QSCALE * v.y);
    int q2 = __float2int_rn(QSCALE * v.z);
    int q3 = __float2int_rn(QSCALE * v.w);
    bool bad = (q0 > 127 || q0 < -127 || q1 > 127 || q1 < -127 ||
                q2 > 127 || q2 < -127 || q3 > 127 || q3 < -127);
    if (bad) {
        q0 = max(-127, min(127, q0)); q1 = max(-127, min(127, q1));
        q2 = max(-127, min(127, q2)); q3 = max(-127, min(127, q3));
        int p = atomicAdd(&g_nclamp, 1);
        if (p < CLCAP) g_clampidx[p] = i >> 6;
    }
    char4 c; c.x = (char)q0; c.y = (char)q1; c.z = (char)q2; c.w = (char)q3;
    *reinterpret_cast<char4*>(g_cb8 + (size_t)i * 4) = c;
}

// ============================================================================
// Screen: int8 IMMA (m16n8k32), 256 thr (8 warps, 2m x 4n, warp tile m32n64).
// CTA = 64 rows x all 8192 codes. Integer scores: s = esq676[col] + acc.
// Per-(warp,row) running min in REGISTERS (quad-shfl shared); candidates =
// codes with s < running_min + TH_INT, appended for exact fp32 rescore.
// SMEM: A 16K | B ring 2x32K | esq676 2x1K  = 83968  (2 CTAs/SM)
// ============================================================================
#define S_A   0u
#define S_B   16384u
#define S_E   81920u
#define SCR_SMEM 83968

__global__ __launch_bounds__(256, 2) void vq_screen() {
    extern __shared__ char sm[];
    const uint32_t sb = smem_u32(sm);
    const int tid = threadIdx.x, lane = tid & 31, w = tid >> 5;
    const int wm = w & 1, wn = w >> 1;
    const int row0 = blockIdx.x * 64;

    // ---- prologue: A (16KB int8), esq676 tile0, B chunk 0 ----
#pragma unroll
    for (int q = 0; q < 4; q++) {
        int lin = q * 256 + tid;
        int r = lin >> 4, c = lin & 15;
        cp16(sb + S_A + r * 256 + ((c * 16) ^ ((r & 7) << 4)),
             g_z8 + (size_t)(row0 + r) * DDIM + c * 16);
    }
    if (tid < 64) cp16(sb + S_E + tid * 16, g_esq676 + tid * 4);
#pragma unroll
    for (int q = 0; q < 8; q++) {
        int lin = q * 256 + tid;
        int r = lin >> 3, c = lin & 7;
        cp16(sb + S_B + r * 128 + ((c * 16) ^ ((r & 7) << 4)),
             g_cb8 + (size_t)r * DDIM + c * 16);
    }
    CPC();

    const uint32_t aBase = sb + S_A + (uint32_t)(wm * 32 + (lane & 15)) * 256;
    const uint32_t aK    = (uint32_t)((lane >> 4) * 16);
    const uint32_t aSw   = (uint32_t)((lane & 7) << 4);
    const uint32_t bRow  = (uint32_t)(wn * 64 + (lane & 7) + ((lane >> 4) & 1) * 8) * 128;
    const uint32_t bK    = (uint32_t)(((lane >> 3) & 1) * 16);

    int myrow[4];
#pragma unroll
    for (int mf = 0; mf < 2; mf++)
#pragma unroll
        for (int h = 0; h < 2; h++)
            myrow[mf * 2 + h] = wm * 32 + mf * 16 + (lane >> 2) + h * 8;

    int lbest[4] = {0x3FFFFFFF, 0x3FFFFFFF, 0x3FFFFFFF, 0x3FFFFFFF};
    int acc[2][8][4];

    for (int cs = 0; cs < 64; cs++) {
        const int it = cs >> 1, ch = cs & 1;
        if (cs + 1 < 64) {
            const int itN = (cs + 1) >> 1, chN = (cs + 1) & 1;
            const uint32_t dstB = sb + S_B + (uint32_t)((cs + 1) & 1) * 32768;
            const int8_t* srcB = g_cb8 + (size_t)(itN * 256) * DDIM + chN * 128;
#pragma unroll
            for (int q = 0; q < 8; q++) {
                int lin = q * 256 + tid;
                int r = lin >> 3, c = lin & 7;
                cp16(dstB + r * 128 + ((c * 16) ^ ((r & 7) << 4)),
                     srcB + (size_t)r * DDIM + c * 16);
            }
            if (chN == 0 && tid < 64)
                cp16(sb + S_E + (uint32_t)(itN & 1) * 1024 + tid * 16,
                     g_esq676 + itN * 256 + tid * 4);
            CPC();
            CPW(1);
        } else {
            CPW(0);
        }
        __syncthreads();

        const uint32_t bufB = sb + S_B + (uint32_t)(cs & 1) * 32768;
        const int* esq_t = reinterpret_cast<const int*>(sm + S_E + (it & 1) * 1024);

        if (ch == 0) {
#pragma unroll
            for (int mf = 0; mf < 2; mf++)
#pragma unroll
                for (int nf = 0; nf < 8; nf++)
#pragma unroll
                    for (int k = 0; k < 4; k++) acc[mf][nf][k] = 0;
        }

#pragma unroll
        for (int ks = 0; ks < 4; ks++) {
            uint32_t a[2][4];
#pragma unroll
            for (int mf = 0; mf < 2; mf++)
                ldmx4(a[mf], aBase + mf * 4096 +
                              (((uint32_t)(ch * 128 + ks * 32) + aK) ^ aSw));
            uint32_t b[4][4];
#pragma unroll
            for (int p = 0; p < 4; p++)
                ldmx4(b[p], bufB + bRow + p * 2048 +
                              (((uint32_t)(ks * 32) + bK) ^ aSw));
#pragma unroll
            for (int mf = 0; mf < 2; mf++)
#pragma unroll
                for (int p = 0; p < 4; p++) {
                    imma16832(acc[mf][2 * p],     a[mf], b[p][0], b[p][1]);
                    imma16832(acc[mf][2 * p + 1], a[mf], b[p][2], b[p][3]);
                }
        }

        if (ch == 1) {
            // integer epilogue: min-tree + quad-shfl row min + guarded appends
#pragma unroll
            for (int mf = 0; mf < 2; mf++)
#pragma unroll
                for (int h = 0; h < 2; h++) {
                    const int ls = mf * 2 + h;
                    int vmin = 0x7FFFFFFF;
#pragma unroll
                    for (int nf = 0; nf < 8; nf++)
#pragma unroll
                        for (int j = 0; j < 2; j++) {
                            int s = esq_t[wn * 64 + nf * 8 + (lane & 3) * 2 + j]
                                  + acc[mf][nf][h * 2 + j];
                            vmin = min(vmin, s);
                        }
                    int q = min(vmin, __shfl_xor_sync(0xffffffffu, vmin, 1));
                    q = min(q, __shfl_xor_sync(0xffffffffu, q, 2));
                    lbest[ls] = min(lbest[ls], q);
                    const int thr = lbest[ls] + TH_INT;
                    if (vmin < thr) {
#pragma unroll
                        for (int nf = 0; nf < 8; nf++)
#pragma unroll
                            for (int j = 0; j < 2; j++) {
                                int s = esq_t[wn * 64 + nf * 8 + (lane & 3) * 2 + j]
                                      + acc[mf][nf][h * 2 + j];
                                if (s < thr) {
                                    int grow = row0 + myrow[ls];
                                    int slot = atomicAdd(&g_ccnt[grow], 1);
                                    if (slot < CAP)
                                        g_cand[grow * CAP + slot] =
                                            it * 256 + wn * 64 + nf * 8 +
                                            (lane & 3) * 2 + j;
                                }
                            }
                    }
                }
        }
        __syncthreads();
    }
}

// ============================================================================
// Exact fp32 rescoring of candidates (1 warp per row); full scan fallback.
// ============================================================================
__global__ __launch_bounds__(256) void vq_exact_cand(const float* __restrict__ z_e,
                                                     const float* __restrict__ cb) {
    const int lane = threadIdx.x & 31;
    const int wid  = (blockIdx.x * 256 + threadIdx.x) >> 5;
    const int nwarps = (gridDim.x * 256) >> 5;
    int nclamp = g_nclamp;
    bool clamp_bad = (nclamp > CLCAP);
    if (nclamp > CLCAP) nclamp = CLCAP;

    for (int row = wid; row < BROWS; row += nwarps) {
        float4 z0 = reinterpret_cast<const float4*>(z_e + (size_t)row * DDIM)[lane * 2];
        float4 z1 = reinterpret_cast<const float4*>(z_e + (size_t)row * DDIM)[lane * 2 + 1];
        float bv = 3.4e38f;
        int   bi = 0x7fffffff;

        auto eval = [&](int k) {
            const float4* e4 = reinterpret_cast<const float4*>(cb + (size_t)k * DDIM);
            float4 e0 = e4[lane * 2], e1 = e4[lane * 2 + 1];
            float d = z0.x * e0.x + z0.y * e0.y + z0.z * e0.z + z0.w * e0.w
                    + z1.x * e1.x + z1.y * e1.y + z1.z * e1.z + z1.w * e1.w;
#pragma unroll
            for (int o = 16; o; o >>= 1) d += __shfl_xor_sync(0xffffffffu, d, o);
            float s = g_esq[k] - d;
            if (s < bv || (s == bv && k < bi)) { bv = s; bi = k; }
        };

        int cnt = g_ccnt[row];
        if (cnt <= CAP && !clamp_bad) {
            for (int i = 0; i < cnt; i++) eval(g_cand[row * CAP + i]);
            for (int j = 0; j < nclamp; j++) eval(g_clampidx[j]);
        } else {
            for (int k = 0; k < KROWS; k++) eval(k);
        }
        if (lane == 0) g_row_idx[row] = bi;
    }
}

// ============================================================================
// Output epilogue (float4 lanes) + parallel final loss
// ============================================================================
__global__ __launch_bounds__(256)
void out_kernel(const float* __restrict__ z_e, const float* __restrict__ cb,
                float* __restrict__ out, long long out_size) {
    __shared__ float red[256];
    const int tid = threadIdx.x;
    const int row0 = blockIdx.x * 64;
    const int rsub = tid >> 6;
    const int c4   = tid & 63;
    float lsum = 0.f;
#pragma unroll 4
    for (int r = rsub; r < 64; r += 4) {
        const int row = row0 + r;
        const int idx = g_row_idx[row];
        float4 ze = reinterpret_cast<const float4*>(z_e + (size_t)row * DDIM)[c4];
        float4 zq = reinterpret_cast<const float4*>(cb + (size_t)idx * DDIM)[c4];
        float4 d;
        d.x = zq.x - ze.x; d.y = zq.y - ze.y; d.z = zq.z - ze.z; d.w = zq.w - ze.w;
        float4 o;
        o.x = ze.x + d.x; o.y = ze.y + d.y; o.z = ze.z + d.z; o.w = ze.w + d.w;
        long long pos = (long long)row * DDIM + c4 * 4;
        if (pos + 3 < out_size)
            reinterpret_cast<float4*>(out)[pos >> 2] = o;
        lsum += d.x * d.x + d.y * d.y + d.z * d.z + d.w * d.w;
    }
    if (tid < 64) {
        long long pos = (long long)BROWS * DDIM + row0 + tid;
        if (pos < out_size) out[pos] = (float)g_row_idx[row0 + tid];
    }
    red[tid] = lsum;
    __syncthreads();
#pragma unroll
    for (int st = 128; st > 0; st >>= 1) {
        if (tid < st) red[tid] += red[tid + st];
        __syncthreads();
    }
    if (tid == 0) g_partial[blockIdx.x] = red[0];
}

__global__ __launch_bounds__(512) void final_kernel(float* __restrict__ out,
                                                    long long out_size) {
    __shared__ float red[512];
    const int tid = threadIdx.x;
    red[tid] = g_partial[tid];
    __syncthreads();
#pragma unroll
    for (int st = 256; st > 0; st >>= 1) {
        if (tid < st) red[tid] += red[tid + st];
        __syncthreads();
    }
    if (tid == 0) {
        float mse = red[0] / ((float)BROWS * (float)DDIM);
        long long pos = (long long)BROWS * DDIM + BROWS;
        if (pos < out_size) out[pos] = 1.25f * mse;
    }
}

// ============================================================================
extern "C" void kernel_launch(void* const* d_in, const int* in_sizes, int n_in,
                              void* d_out, int out_size) {
    const float* z_e = (const float*)d_in[0];
    const float* cb  = (const float*)d_in[1];
    float* out       = (float*)d_out;

    prep_kernel<<<KROWS / 8, 256>>>(cb);
    quant_z<<<(BROWS * DDIM / 4) / 256, 256>>>(z_e);
    quant_cb<<<(KROWS * DDIM / 4) / 256, 256>>>(cb);

    cudaFuncSetAttribute(vq_screen, cudaFuncAttributeMaxDynamicSharedMemorySize,
                         SCR_SMEM);
    vq_screen<<<BROWS / 64, 256, SCR_SMEM>>>();

    vq_exact_cand<<<256, 256>>>(z_e, cb);
    out_kernel<<<BROWS / 64, 256>>>(z_e, cb, out, (long long)out_size);
    final_kernel<<<1, 512>>>(out, (long long)out_size);
}

// round 16
// speedup vs baseline: 1.0665x; 1.0665x over previous
#include <cuda_runtime.h>
#include <cstdint>

#define BROWS  32768
#define KROWS  8192
#define DDIM   256
#define QSCALE 26.0f
#define TH_INT 2200
#define CAP    256
#define CLCAP  64

// ---------------- device globals (no cudaMalloc allowed) --------------------
__device__ __align__(16) int8_t g_z8[BROWS * DDIM];    // round(-26 * z)
__device__ __align__(16) int8_t g_cb8[KROWS * DDIM];   // round( 26 * e)
__device__ __align__(16) float  g_esq[KROWS];          // 0.5*||e||^2 exact
__device__ __align__(16) int    g_esq676[KROWS];       // round(676 * esq)
__device__ int   g_row_idx[BROWS];
__device__ int   g_ccnt[BROWS];
__device__ int   g_cand[BROWS * CAP];                  // 32 MB
__device__ int   g_nclamp;
__device__ int   g_clampidx[CLCAP];
__device__ float g_partial[BROWS / 64];

// ---------------- asm helpers (baseline PTX only) ----------------------------
__device__ __forceinline__ uint32_t smem_u32(const void* p) {
    uint32_t a;
    asm("{ .reg .u64 t; cvta.to.shared.u64 t, %1; cvt.u32.u64 %0, t; }"
        : "=r"(a) : "l"(p));
    return a;
}
__device__ __forceinline__ void ldmx4(uint32_t r[4], uint32_t addr) {
    asm volatile("ldmatrix.sync.aligned.m8n8.x4.shared.b16 {%0,%1,%2,%3}, [%4];\n"
        : "=r"(r[0]), "=r"(r[1]), "=r"(r[2]), "=r"(r[3]) : "r"(addr));
}
// int8 MMA: m16n8k32, s32 accumulate. Fragments byte-identical to f16 m16n8k16.
__device__ __forceinline__ void imma16832(int c[4], const uint32_t a[4],
                                          uint32_t b0, uint32_t b1) {
    asm volatile(
        "mma.sync.aligned.m16n8k32.row.col.s32.s8.s8.s32 "
        "{%0,%1,%2,%3}, {%4,%5,%6,%7}, {%8,%9}, {%0,%1,%2,%3};\n"
        : "+r"(c[0]), "+r"(c[1]), "+r"(c[2]), "+r"(c[3])
        : "r"(a[0]), "r"(a[1]), "r"(a[2]), "r"(a[3]), "r"(b0), "r"(b1));
}
__device__ __forceinline__ void cp16(uint32_t dst, const void* src) {
    asm volatile("cp.async.cg.shared.global [%0], [%1], 16;\n"
        :: "r"(dst), "l"(src));
}
#define CPC()  asm volatile("cp.async.commit_group;\n" ::: "memory")
#define CPW(n) asm volatile("cp.async.wait_group %0;\n" :: "n"(n) : "memory")

// ---------------- prep: esq, esq676, counter resets ---------------------------
__global__ void prep_kernel(const float* __restrict__ cb) {
    int gtid = blockIdx.x * 256 + threadIdx.x;
    if (gtid < BROWS) g_ccnt[gtid] = 0;
    if (gtid == 0) g_nclamp = 0;
    int row = blockIdx.x * 8 + (threadIdx.x >> 5);
    if (row >= KROWS) return;
    int lane = threadIdx.x & 31;
    const float4* p = reinterpret_cast<const float4*>(cb + (size_t)row * DDIM);
    float s = 0.f;
#pragma unroll
    for (int i = 0; i < 2; i++) {
        float4 v = p[lane + 32 * i];
        s += v.x * v.x + v.y * v.y + v.z * v.z + v.w * v.w;
    }
#pragma unroll
    for (int o = 16; o; o >>= 1) s += __shfl_down_sync(0xffffffffu, s, o);
    if (lane == 0) {
        float e = 0.5f * s;
        g_esq[row] = e;
        g_esq676[row] = __float2int_rn(676.0f * e);
    }
}

// ---------------- quantizers -------------------------------------------------
__global__ void quant_z(const float* __restrict__ src) {
    int i = blockIdx.x * 256 + threadIdx.x;
    if (i >= BROWS * DDIM / 4) return;
    float4 v = reinterpret_cast<const float4*>(src)[i];
    int q0 = __float2int_rn(-QSCALE * v.x);
    int q1 = __float2int_rn(-QSCALE * v.y);
    int q2 = __float2int_rn(-QSCALE * v.z);
    int q3 = __float2int_rn(-QSCALE * v.w);
    bool bad = (q0 > 127 || q0 < -127 || q1 > 127 || q1 < -127 ||
                q2 > 127 || q2 < -127 || q3 > 127 || q3 < -127);
    if (bad) {
        q0 = max(-127, min(127, q0)); q1 = max(-127, min(127, q1));
        q2 = max(-127, min(127, q2)); q3 = max(-127, min(127, q3));
        g_ccnt[i >> 6] = 0x40000000;   // sentinel: force exact full scan
    }
    char4 c; c.x = (char)q0; c.y = (char)q1; c.z = (char)q2; c.w = (char)q3;
    *reinterpret_cast<char4*>(g_z8 + (size_t)i * 4) = c;
}

__global__ void quant_cb(const float* __restrict__ src) {
    int i = blockIdx.x * 256 + threadIdx.x;
    if (i >= KROWS * DDIM / 4) return;
    float4 v = reinterpret_cast<const float4*>(src)[i];
    int q0 = __float2int_rn(QSCALE * v.x);
    int q1 = __float2int_rn(QSCALE * v.y);
    int q2 = __float2int_rn(QSCALE * v.z);
    int q3 = __float2int_rn(QSCALE * v.w);
    bool bad = (q0 > 127 || q0 < -127 || q1 > 127 || q1 < -127 ||
                q2 > 127 || q2 < -127 || q3 > 127 || q3 < -127);
    if (bad) {
        q0 = max(-127, min(127, q0)); q1 = max(-127, min(127, q1));
        q2 = max(-127, min(127, q2)); q3 = max(-127, min(127, q3));
        int p = atomicAdd(&g_nclamp, 1);
        if (p < CLCAP) g_clampidx[p] = i >> 6;
    }
    char4 c; c.x = (char)q0; c.y = (char)q1; c.z = (char)q2; c.w = (char)q3;
    *reinterpret_cast<char4*>(g_cb8 + (size_t)i * 4) = c;
}

// ============================================================================
// Screen: int8 IMMA (m16n8k32), 256 thr (8 warps, 2m x 4n, warp tile m32n64).
// CTA = 64 rows x all 8192 codes. Integer scores: s = esq676[col] + acc.
// Running per-row global min shared ACROSS warps via SMEM table (unique
// writer per (wn,row); ordered by the per-tile __syncthreads) -> tight
// thresholds, no overflow tail. Candidates rescored exactly in fp32.
// SMEM: A 16K | B ring 2x32K | esq676 2x1K | rowmin 4x64 ints  (2 CTAs/SM)
// ============================================================================
#define S_A   0u
#define S_B   16384u
#define S_E   81920u
#define S_RW  83968u
#define SCR_SMEM 84992

__global__ __launch_bounds__(256, 2) void vq_screen() {
    extern __shared__ char sm[];
    const uint32_t sb = smem_u32(sm);
    int* rbw = reinterpret_cast<int*>(sm + S_RW);   // [wn][64 rows]
    const int tid = threadIdx.x, lane = tid & 31, w = tid >> 5;
    const int wm = w & 1, wn = w >> 1;
    const int row0 = blockIdx.x * 64;

    if (tid < 256) rbw[tid] = 0x3FFFFFFF;

    // ---- prologue: A (16KB int8), esq676 tile0, B chunk 0 ----
#pragma unroll
    for (int q = 0; q < 4; q++) {
        int lin = q * 256 + tid;
        int r = lin >> 4, c = lin & 15;
        cp16(sb + S_A + r * 256 + ((c * 16) ^ ((r & 7) << 4)),
             g_z8 + (size_t)(row0 + r) * DDIM + c * 16);
    }
    if (tid < 64) cp16(sb + S_E + tid * 16, g_esq676 + tid * 4);
#pragma unroll
    for (int q = 0; q < 8; q++) {
        int lin = q * 256 + tid;
        int r = lin >> 3, c = lin & 7;
        cp16(sb + S_B + r * 128 + ((c * 16) ^ ((r & 7) << 4)),
             g_cb8 + (size_t)r * DDIM + c * 16);
    }
    CPC();

    const uint32_t aBase = sb + S_A + (uint32_t)(wm * 32 + (lane & 15)) * 256;
    const uint32_t aK    = (uint32_t)((lane >> 4) * 16);
    const uint32_t aSw   = (uint32_t)((lane & 7) << 4);
    const uint32_t bRow  = (uint32_t)(wn * 64 + (lane & 7) + ((lane >> 4) & 1) * 8) * 128;
    const uint32_t bK    = (uint32_t)(((lane >> 3) & 1) * 16);

    int myrow[4];
#pragma unroll
    for (int mf = 0; mf < 2; mf++)
#pragma unroll
        for (int h = 0; h < 2; h++)
            myrow[mf * 2 + h] = wm * 32 + mf * 16 + (lane >> 2) + h * 8;

    int lbest[4] = {0x3FFFFFFF, 0x3FFFFFFF, 0x3FFFFFFF, 0x3FFFFFFF};
    int acc[2][8][4];

    for (int cs = 0; cs < 64; cs++) {
        const int it = cs >> 1, ch = cs & 1;
        if (cs + 1 < 64) {
            const int itN = (cs + 1) >> 1, chN = (cs + 1) & 1;
            const uint32_t dstB = sb + S_B + (uint32_t)((cs + 1) & 1) * 32768;
            const int8_t* srcB = g_cb8 + (size_t)(itN * 256) * DDIM + chN * 128;
#pragma unroll
            for (int q = 0; q < 8; q++) {
                int lin = q * 256 + tid;
                int r = lin >> 3, c = lin & 7;
                cp16(dstB + r * 128 + ((c * 16) ^ ((r & 7) << 4)),
                     srcB + (size_t)r * DDIM + c * 16);
            }
            if (chN == 0 && tid < 64)
                cp16(sb + S_E + (uint32_t)(itN & 1) * 1024 + tid * 16,
                     g_esq676 + itN * 256 + tid * 4);
            CPC();
            CPW(1);
        } else {
            CPW(0);
        }
        __syncthreads();

        const uint32_t bufB = sb + S_B + (uint32_t)(cs & 1) * 32768;
        const int* esq_t = reinterpret_cast<const int*>(sm + S_E + (it & 1) * 1024);

        if (ch == 0) {
#pragma unroll
            for (int mf = 0; mf < 2; mf++)
#pragma unroll
                for (int nf = 0; nf < 8; nf++)
#pragma unroll
                    for (int k = 0; k < 4; k++) acc[mf][nf][k] = 0;
        }

#pragma unroll
        for (int ks = 0; ks < 4; ks++) {
            uint32_t a[2][4];
#pragma unroll
            for (int mf = 0; mf < 2; mf++)
                ldmx4(a[mf], aBase + mf * 4096 +
                              (((uint32_t)(ch * 128 + ks * 32) + aK) ^ aSw));
            uint32_t b[4][4];
#pragma unroll
            for (int p = 0; p < 4; p++)
                ldmx4(b[p], bufB + bRow + p * 2048 +
                              (((uint32_t)(ks * 32) + bK) ^ aSw));
#pragma unroll
            for (int mf = 0; mf < 2; mf++)
#pragma unroll
                for (int p = 0; p < 4; p++) {
                    imma16832(acc[mf][2 * p],     a[mf], b[p][0], b[p][1]);
                    imma16832(acc[mf][2 * p + 1], a[mf], b[p][2], b[p][3]);
                }
        }

        if (ch == 1) {
            // integer epilogue: cross-warp-shared running min + guarded appends
#pragma unroll
            for (int mf = 0; mf < 2; mf++)
#pragma unroll
                for (int h = 0; h < 2; h++) {
                    const int ls = mf * 2 + h;
                    int vmin = 0x7FFFFFFF;
#pragma unroll
                    for (int nf = 0; nf < 8; nf++)
#pragma unroll
                        for (int j = 0; j < 2; j++) {
                            int s = esq_t[wn * 64 + nf * 8 + (lane & 3) * 2 + j]
                                  + acc[mf][nf][h * 2 + j];
                            vmin = min(vmin, s);
                        }
                    int q = min(vmin, __shfl_xor_sync(0xffffffffu, vmin, 1));
                    q = min(q, __shfl_xor_sync(0xffffffffu, q, 2));
                    // fold cross-warp published mins (<=1 tile lag, safe)
                    const int r = myrow[ls];
                    int shmin = min(min(rbw[r], rbw[64 + r]),
                                    min(rbw[128 + r], rbw[192 + r]));
                    lbest[ls] = min(lbest[ls], min(q, shmin));
                    const int thr = lbest[ls] + TH_INT;
                    if (vmin < thr) {
#pragma unroll
                        for (int nf = 0; nf < 8; nf++)
#pragma unroll
                            for (int j = 0; j < 2; j++) {
                                int s = esq_t[wn * 64 + nf * 8 + (lane & 3) * 2 + j]
                                      + acc[mf][nf][h * 2 + j];
                                if (s < thr) {
                                    int grow = row0 + r;
                                    int slot = atomicAdd(&g_ccnt[grow], 1);
                                    if (slot < CAP)
                                        g_cand[grow * CAP + slot] =
                                            it * 256 + wn * 64 + nf * 8 +
                                            (lane & 3) * 2 + j;
                                }
                            }
                    }
                }
            // publish this warp's running row mins (unique writer per (wn,row))
            if ((lane & 3) == 0) {
#pragma unroll
                for (int s2 = 0; s2 < 4; s2++)
                    rbw[wn * 64 + myrow[s2]] = lbest[s2];
            }
        }
        __syncthreads();
    }
}

// ============================================================================
// Exact fp32 rescoring of candidates (1 warp per row); full scan fallback.
// ============================================================================
__global__ __launch_bounds__(256) void vq_exact_cand(const float* __restrict__ z_e,
                                                     const float* __restrict__ cb) {
    const int lane = threadIdx.x & 31;
    const int wid  = (blockIdx.x * 256 + threadIdx.x) >> 5;
    const int nwarps = (gridDim.x * 256) >> 5;
    int nclamp = g_nclamp;
    bool clamp_bad = (nclamp > CLCAP);
    if (nclamp > CLCAP) nclamp = CLCAP;

    for (int row = wid; row < BROWS; row += nwarps) {
        float4 z0 = reinterpret_cast<const float4*>(z_e + (size_t)row * DDIM)[lane * 2];
        float4 z1 = reinterpret_cast<const float4*>(z_e + (size_t)row * DDIM)[lane * 2 + 1];
        float bv = 3.4e38f;
        int   bi = 0x7fffffff;

        auto eval = [&](int k) {
            const float4* e4 = reinterpret_cast<const float4*>(cb + (size_t)k * DDIM);
            float4 e0 = e4[lane * 2], e1 = e4[lane * 2 + 1];
            float d = z0.x * e0.x + z0.y * e0.y + z0.z * e0.z + z0.w * e0.w
                    + z1.x * e1.x + z1.y * e1.y + z1.z * e1.z + z1.w * e1.w;
#pragma unroll
            for (int o = 16; o; o >>= 1) d += __shfl_xor_sync(0xffffffffu, d, o);
            float s = g_esq[k] - d;
            if (s < bv || (s == bv && k < bi)) { bv = s; bi = k; }
        };

        int cnt = g_ccnt[row];
        if (cnt <= CAP && !clamp_bad) {
            for (int i = 0; i < cnt; i++) eval(g_cand[row * CAP + i]);
            for (int j = 0; j < nclamp; j++) eval(g_clampidx[j]);
        } else {
            for (int k = 0; k < KROWS; k++) eval(k);
        }
        if (lane == 0) g_row_idx[row] = bi;
    }
}

// ============================================================================
// Output epilogue (float4 lanes) + parallel final loss
// ============================================================================
__global__ __launch_bounds__(256)
void out_kernel(const float* __restrict__ z_e, const float* __restrict__ cb,
                float* __restrict__ out, long long out_size) {
    __shared__ float red[256];
    const int tid = threadIdx.x;
    const int row0 = blockIdx.x * 64;
    const int rsub = tid >> 6;
    const int c4   = tid & 63;
    float lsum = 0.f;
#pragma unroll 4
    for (int r = rsub; r < 64; r += 4) {
        const int row = row0 + r;
        const int idx = g_row_idx[row];
        float4 ze = reinterpret_cast<const float4*>(z_e + (size_t)row * DDIM)[c4];
        float4 zq = reinterpret_cast<const float4*>(cb + (size_t)idx * DDIM)[c4];
        float4 d;
        d.x = zq.x - ze.x; d.y = zq.y - ze.y; d.z = zq.z - ze.z; d.w = zq.w - ze.w;
        float4 o;
        o.x = ze.x + d.x; o.y = ze.y + d.y; o.z = ze.z + d.z; o.w = ze.w + d.w;
        long long pos = (long long)row * DDIM + c4 * 4;
        if (pos + 3 < out_size)
            reinterpret_cast<float4*>(out)[pos >> 2] = o;
        lsum += d.x * d.x + d.y * d.y + d.z * d.z + d.w * d.w;
    }
    if (tid < 64) {
        long long pos = (long long)BROWS * DDIM + row0 + tid;
        if (pos < out_size) out[pos] = (float)g_row_idx[row0 + tid];
    }
    red[tid] = lsum;
    __syncthreads();
#pragma unroll
    for (int st = 128; st > 0; st >>= 1) {
        if (tid < st) red[tid] += red[tid + st];
        __syncthreads();
    }
    if (tid == 0) g_partial[blockIdx.x] = red[0];
}

__global__ __launch_bounds__(512) void final_kernel(float* __restrict__ out,
                                                    long long out_size) {
    __shared__ float red[512];
    const int tid = threadIdx.x;
    red[tid] = g_partial[tid];
    __syncthreads();
#pragma unroll
    for (int st = 256; st > 0; st >>= 1) {
        if (tid < st) red[tid] += red[tid + st];
        __syncthreads();
    }
    if (tid == 0) {
        float mse = red[0] / ((float)BROWS * (float)DDIM);
        long long pos = (long long)BROWS * DDIM + BROWS;
        if (pos < out_size) out[pos] = 1.25f * mse;
    }
}

// ============================================================================
extern "C" void kernel_launch(void* const* d_in, const int* in_sizes, int n_in,
                              void* d_out, int out_size) {
    const float* z_e = (const float*)d_in[0];
    const float* cb  = (const float*)d_in[1];
    float* out       = (float*)d_out;

    prep_kernel<<<KROWS / 8, 256>>>(cb);
    quant_z<<<(BROWS * DDIM / 4) / 256, 256>>>(z_e);
    quant_cb<<<(KROWS * DDIM / 4) / 256, 256>>>(cb);

    cudaFuncSetAttribute(vq_screen, cudaFuncAttributeMaxDynamicSharedMemorySize,
                         SCR_SMEM);
    vq_screen<<<BROWS / 64, 256, SCR_SMEM>>>();

    vq_exact_cand<<<256, 256>>>(z_e, cb);
    out_kernel<<<BROWS / 64, 256>>>(z_e, cb, out, (long long)out_size);
    final_kernel<<<1, 512>>>(out, (long long)out_size);
}

// round 17
// speedup vs baseline: 4.0959x; 3.8406x over previous
#include <cuda_runtime.h>
#include <cuda_fp16.h>
#include <cstdint>

#define BROWS  32768
#define KROWS  8192
#define DDIM   256
#define TH1    0.05f
#define TH2    1e-3f
#define RCAP   8192
#define R2CAP  1024

// ---------------- device globals (no cudaMalloc allowed) --------------------
__device__ __align__(16) __half g_z_hi[BROWS * DDIM];   // hi/lo of (-z)
__device__ __align__(16) __half g_z_lo[BROWS * DDIM];
__device__ __align__(16) __half g_cb_hi[KROWS * DDIM];
__device__ __align__(16) __half g_cb_lo[KROWS * DDIM];
__device__ __align__(16) float g_esq[KROWS];
__device__ int   g_row_idx[BROWS];
__device__ int   g_nrisky;
__device__ int   g_risky[RCAP];
__device__ float g_rb[RCAP * 8];
__device__ float g_rs[RCAP * 8];
__device__ int   g_ri[RCAP * 8];
__device__ int   g_nr2;
__device__ int   g_r2[R2CAP];
__device__ float g_partial[BROWS / 64];

// ---------------- asm helpers (baseline PTX only) ----------------------------
__device__ __forceinline__ uint32_t smem_u32(const void* p) {
    uint32_t a;
    asm("{ .reg .u64 t; cvta.to.shared.u64 t, %1; cvt.u32.u64 %0, t; }"
        : "=r"(a) : "l"(p));
    return a;
}
__device__ __forceinline__ void ldmx4(uint32_t r[4], uint32_t addr) {
    asm volatile("ldmatrix.sync.aligned.m8n8.x4.shared.b16 {%0,%1,%2,%3}, [%4];\n"
        : "=r"(r[0]), "=r"(r[1]), "=r"(r[2]), "=r"(r[3]) : "r"(addr));
}
__device__ __forceinline__ void mma16816(float c[4], const uint32_t a[4],
                                         uint32_t b0, uint32_t b1) {
    asm volatile(
        "mma.sync.aligned.m16n8k16.row.col.f32.f16.f16.f32 "
        "{%0,%1,%2,%3}, {%4,%5,%6,%7}, {%8,%9}, {%0,%1,%2,%3};\n"
        : "+f"(c[0]), "+f"(c[1]), "+f"(c[2]), "+f"(c[3])
        : "r"(a[0]), "r"(a[1]), "r"(a[2]), "r"(a[3]), "r"(b0), "r"(b1));
}
__device__ __forceinline__ void cp16(uint32_t dst, const void* src) {
    asm volatile("cp.async.cg.shared.global [%0], [%1], 16;\n"
        :: "r"(dst), "l"(src));
}
#define CPC()  asm volatile("cp.async.commit_group;\n" ::: "memory")
#define CPW(n) asm volatile("cp.async.wait_group %0;\n" :: "n"(n) : "memory")

__device__ __forceinline__ void merge3(float& b, float& s, int& i,
                                       float ob, float os, int oi) {
    if (ob < b || (ob == b && oi < i)) {
        s = fminf(b, os); b = ob; i = oi;
    } else {
        s = fminf(s, ob);
    }
}

// ---------------- prep kernels ----------------------------------------------
__global__ void split_kernel(const float* __restrict__ src,
                             __half* __restrict__ hi,
                             __half* __restrict__ lo, int n4, float sign) {
    int i = blockIdx.x * blockDim.x + threadIdx.x;
    if (i >= n4) return;
    float4 v = reinterpret_cast<const float4*>(src)[i];
    v.x *= sign; v.y *= sign; v.z *= sign; v.w *= sign;
    __half h0 = __float2half(v.x), h1 = __float2half(v.y);
    __half h2 = __float2half(v.z), h3 = __float2half(v.w);
    __half2 hp0; hp0.x = h0; hp0.y = h1;
    __half2 hp1; hp1.x = h2; hp1.y = h3;
    __half2 lp0, lp1;
    lp0.x = __float2half(v.x - __half2float(h0));
    lp0.y = __float2half(v.y - __half2float(h1));
    lp1.x = __float2half(v.z - __half2float(h2));
    lp1.y = __float2half(v.w - __half2float(h3));
    reinterpret_cast<__half2*>(hi)[i * 2 + 0] = hp0;
    reinterpret_cast<__half2*>(hi)[i * 2 + 1] = hp1;
    reinterpret_cast<__half2*>(lo)[i * 2 + 0] = lp0;
    reinterpret_cast<__half2*>(lo)[i * 2 + 1] = lp1;
}

__global__ void esq_kernel(const float* __restrict__ cb) {
    if (blockIdx.x == 0 && threadIdx.x == 0) { g_nrisky = 0; g_nr2 = 0; }
    int row = blockIdx.x * 8 + (threadIdx.x >> 5);
    if (row >= KROWS) return;
    int lane = threadIdx.x & 31;
    const float4* p = reinterpret_cast<const float4*>(cb + (size_t)row * DDIM);
    float s = 0.f;
#pragma unroll
    for (int i = 0; i < 2; i++) {
        float4 v = p[lane + 32 * i];
        s += v.x * v.x + v.y * v.y + v.z * v.z + v.w * v.w;
    }
#pragma unroll
    for (int o = 16; o; o >>= 1) s += __shfl_down_sync(0xffffffffu, s, o);
    if (lane == 0) g_esq[row] = 0.5f * s;
}

// ============================================================================
// Screen: fp32-acc HMMA, 256 threads (8 warps, m32n64), 2 CTAs per SM.
// CTA tile: 64 rows x 256 codes; K streamed in 64-dim chunks (B ring 2x32K).
// Each CTA scans all 8192 codes -> direct index write + risky flag.
// SMEM: A 32K | B ring 2x32K | esq 2x1K | red 3K  = ~101K  (2 CTAs/SM)
// ============================================================================
#define S_A   0u
#define S_B   32768u
#define S_E   98304u
#define S_RED 100352u
#define SCR_SMEM 103424

__global__ __launch_bounds__(256, 2) void vq_screen() {
    extern __shared__ char sm[];
    const uint32_t sb = smem_u32(sm);
    const int tid = threadIdx.x, lane = tid & 31, w = tid >> 5;
    const int wm = w & 1, wn = w >> 1;          // 2m x 4n warp grid
    const int row0 = blockIdx.x * 64;

    // ---- prologue: A (32KB, 64 rows x 512B), esq tile0, B chunk-step 0 ----
#pragma unroll
    for (int q = 0; q < 8; q++) {
        int lin = q * 256 + tid;
        int r = lin >> 5, c = lin & 31;
        cp16(sb + S_A + r * 512 + ((c * 16) ^ ((r & 7) << 4)),
             g_z_hi + (size_t)(row0 + r) * DDIM + c * 8);
    }
    if (tid < 64) cp16(sb + S_E + tid * 16, g_esq + tid * 4);
#pragma unroll
    for (int q = 0; q < 8; q++) {
        int lin = q * 256 + tid;
        int r = lin >> 3, c = lin & 7;    // 256 code rows x 128B
        cp16(sb + S_B + r * 128 + ((c * 16) ^ ((r & 7) << 4)),
             g_cb_hi + (size_t)r * DDIM + c * 8);
    }
    CPC();

    const uint32_t aBase = sb + S_A + (uint32_t)(wm * 32 + (lane & 15)) * 512;
    const uint32_t aK    = (uint32_t)((lane >> 4) * 16);
    const uint32_t aSw   = (uint32_t)((lane & 7) << 4);
    const uint32_t bRow  = (uint32_t)(wn * 64 + (lane & 7) + ((lane >> 4) & 1) * 8) * 128;
    const uint32_t bK    = (uint32_t)(((lane >> 3) & 1) * 16);

    float bestv[4], secv[4];
    int   besti[4];
#pragma unroll
    for (int s = 0; s < 4; s++) { bestv[s] = 3.4e38f; secv[s] = 3.4e38f; besti[s] = 0; }

    float acc[2][8][4];

    for (int cs = 0; cs < 128; cs++) {
        const int it = cs >> 2, ch = cs & 3;
        if (cs + 1 < 128) {
            const int itN = (cs + 1) >> 2, chN = (cs + 1) & 3;
            const uint32_t dstB = sb + S_B + (uint32_t)((cs + 1) & 1) * 32768;
            const __half* srcB = g_cb_hi + (size_t)(itN * 256) * DDIM + chN * 64;
#pragma unroll
            for (int q = 0; q < 8; q++) {
                int lin = q * 256 + tid;
                int r = lin >> 3, c = lin & 7;
                cp16(dstB + r * 128 + ((c * 16) ^ ((r & 7) << 4)),
                     srcB + (size_t)r * DDIM + c * 8);
            }
            if (chN == 0 && tid < 64)
                cp16(sb + S_E + (uint32_t)(itN & 1) * 1024 + tid * 16,
                     g_esq + itN * 256 + tid * 4);
            CPC();
            CPW(1);
        } else {
            CPW(0);
        }
        __syncthreads();

        const uint32_t bufB = sb + S_B + (uint32_t)(cs & 1) * 32768;
        const float* esq_t = reinterpret_cast<const float*>(sm + S_E + (it & 1) * 1024);

        if (ch == 0) {
            // init accumulators with esq -> MMA produces final scores
#pragma unroll
            for (int nf = 0; nf < 8; nf++)
#pragma unroll
                for (int j = 0; j < 2; j++) {
                    float e = esq_t[wn * 64 + nf * 8 + (lane & 3) * 2 + j];
#pragma unroll
                    for (int mf = 0; mf < 2; mf++)
#pragma unroll
                        for (int h = 0; h < 2; h++)
                            acc[mf][nf][h * 2 + j] = e;
                }
        }

#pragma unroll
        for (int ks = 0; ks < 4; ks++) {
            uint32_t a[2][4];
#pragma unroll
            for (int mf = 0; mf < 2; mf++)
                ldmx4(a[mf], aBase + mf * 8192 +
                              (((uint32_t)(ch * 128 + ks * 32) + aK) ^ aSw));
            uint32_t b[4][4];
#pragma unroll
            for (int p = 0; p < 4; p++)
                ldmx4(b[p], bufB + bRow + p * 2048 +
                              (((uint32_t)(ks * 32) + bK) ^ aSw));
#pragma unroll
            for (int mf = 0; mf < 2; mf++)
#pragma unroll
                for (int p = 0; p < 4; p++) {
                    mma16816(acc[mf][2 * p],     a[mf], b[p][0], b[p][1]);
                    mma16816(acc[mf][2 * p + 1], a[mf], b[p][2], b[p][3]);
                }
        }

        if (ch == 3) {
            // epilogue: per-slot min-tree + guarded detailed update
#pragma unroll
            for (int mf = 0; mf < 2; mf++)
#pragma unroll
                for (int h = 0; h < 2; h++) {
                    const int s = mf * 2 + h;
                    float v = acc[mf][0][h * 2];
#pragma unroll
                    for (int nf = 0; nf < 8; nf++)
#pragma unroll
                        for (int j = 0; j < 2; j++)
                            if (nf + j > 0) v = fminf(v, acc[mf][nf][h * 2 + j]);
                    if (v < secv[s]) {
#pragma unroll
                        for (int nf = 0; nf < 8; nf++)
#pragma unroll
                            for (int j = 0; j < 2; j++) {
                                float sc = acc[mf][nf][h * 2 + j];
                                int idx = it * 256 + wn * 64 + nf * 8 +
                                          (lane & 3) * 2 + j;
                                if (sc < bestv[s]) {
                                    secv[s] = bestv[s]; bestv[s] = sc; besti[s] = idx;
                                } else if (sc < secv[s]) {
                                    secv[s] = sc;
                                }
                            }
                    }
                }
        }
        __syncthreads();
    }

    // ---- quad reduction (lane&3 share a row) ----
#pragma unroll
    for (int s = 0; s < 4; s++) {
#pragma unroll
        for (int off = 1; off < 4; off <<= 1) {
            float ob = __shfl_xor_sync(0xffffffffu, bestv[s], off);
            float os = __shfl_xor_sync(0xffffffffu, secv[s], off);
            int   oi = __shfl_xor_sync(0xffffffffu, besti[s], off);
            merge3(bestv[s], secv[s], besti[s], ob, os, oi);
        }
    }
    // ---- cross-warp merge over wn (4 groups), 64 rows ----
    float* bR = reinterpret_cast<float*>(sm + S_RED);
    float* sR = bR + 256;
    int*   iR = reinterpret_cast<int*>(bR + 512);
    if ((lane & 3) == 0) {
#pragma unroll
        for (int s = 0; s < 4; s++) {
            int r = wm * 32 + (s >> 1) * 16 + (lane >> 2) + (s & 1) * 8;
            bR[wn * 64 + r] = bestv[s];
            sR[wn * 64 + r] = secv[s];
            iR[wn * 64 + r] = besti[s];
        }
    }
    __syncthreads();
    if (tid < 64) {
        float b = bR[tid], s = sR[tid];
        int   i = iR[tid];
#pragma unroll
        for (int g2 = 1; g2 < 4; g2++)
            merge3(b, s, i, bR[g2 * 64 + tid], sR[g2 * 64 + tid], iR[g2 * 64 + tid]);
        const int row = row0 + tid;
        g_row_idx[row] = i;
        if (s - b < TH1) {
            int p = atomicAdd(&g_nrisky, 1);
            if (p < RCAP) g_risky[p] = row;
        }
    }
}

// ============================================================================
// Rescue: fp16 3-term split (fp32 acc). 32 risky rows x 1024-code slice per CTA.
// grid (32, 8); CTA strides over slot groups.
// ============================================================================
#define R_AH  0u
#define R_AL  16384u
#define R_B   32768u
#define R_E   163840u
#define R_RED 164352u
#define RES_SMEM 165888

__global__ __launch_bounds__(256, 1) void vq_rescue() {
    int count = g_nrisky; if (count > RCAP) count = RCAP;

    extern __shared__ char sm[];
    const uint32_t sb = smem_u32(sm);
    __shared__ int ridx_s[32];
    const int tid = threadIdx.x, lane = tid & 31, w = tid >> 5;
    const int mm = w & 1, nn = w >> 1;
    const int code0 = blockIdx.y * 1024;

    const uint32_t aRow = (uint32_t)(mm * 16 + (lane & 15)) * 512;
    const uint32_t aK   = (uint32_t)((lane >> 4) * 16);
    const uint32_t aSw  = (uint32_t)((lane & 7) << 4);
    const uint32_t bRow = (uint32_t)(nn * 16 + (lane & 7) + ((lane >> 4) & 1) * 8) * 512;
    const uint32_t bK   = (uint32_t)(((lane >> 3) & 1) * 16);

    for (int base = blockIdx.x * 32; base < count; base += 32 * 32) {
        if (tid < 32) {
            int gp = base + tid;
            ridx_s[tid] = (gp < count) ? g_risky[gp] : g_risky[base];
        }
        __syncthreads();

#pragma unroll
        for (int q = 0; q < 4; q++) {
            int lin = q * 256 + tid;
            int r = lin >> 5, c = lin & 31;
            uint32_t swo = (uint32_t)r * 512 + ((c * 16) ^ ((r & 7) << 4));
            int gr = ridx_s[r];
            cp16(sb + R_AH + swo, g_z_hi + (size_t)gr * DDIM + c * 8);
            cp16(sb + R_AL + swo, g_z_lo + (size_t)gr * DDIM + c * 8);
        }
        if (tid < 16) cp16(sb + R_E + tid * 16, g_esq + code0 + tid * 4);
#pragma unroll
        for (int q = 0; q < 8; q++) {
            int lin = q * 256 + tid;
            int r = lin >> 5, c = lin & 31;
            uint32_t swo = (uint32_t)r * 512 + ((c * 16) ^ ((r & 7) << 4));
            cp16(sb + R_B + swo,         g_cb_hi + (size_t)(code0 + r) * DDIM + c * 8);
            cp16(sb + R_B + 32768 + swo, g_cb_lo + (size_t)(code0 + r) * DDIM + c * 8);
        }
        CPC();

        float bestv[2], secv[2];
        int   besti[2];
#pragma unroll
        for (int s = 0; s < 2; s++) { bestv[s] = 3.4e38f; secv[s] = 3.4e38f; besti[s] = 0; }

        for (int t = 0; t < 16; t++) {
            if (t + 1 < 16) {
                const int cnext = code0 + (t + 1) * 64;
                uint32_t dstB = sb + R_B + (uint32_t)((t + 1) & 1) * 65536;
#pragma unroll
                for (int q = 0; q < 8; q++) {
                    int lin = q * 256 + tid;
                    int r = lin >> 5, c = lin & 31;
                    uint32_t swo = (uint32_t)r * 512 + ((c * 16) ^ ((r & 7) << 4));
                    cp16(dstB + swo,         g_cb_hi + (size_t)(cnext + r) * DDIM + c * 8);
                    cp16(dstB + 32768 + swo, g_cb_lo + (size_t)(cnext + r) * DDIM + c * 8);
                }
                if (tid < 16)
                    cp16(sb + R_E + (uint32_t)((t + 1) & 1) * 256 + tid * 16,
                         g_esq + cnext + tid * 4);
                CPC();
                CPW(1);
            } else {
                CPW(0);
            }
            __syncthreads();

            const uint32_t bufHi = sb + R_B + (uint32_t)(t & 1) * 65536;
            const uint32_t bufLo = bufHi + 32768;
            const float* esq_t = reinterpret_cast<const float*>(sm + R_E + (t & 1) * 256);

            float acc[2][4];
#pragma unroll
            for (int nf = 0; nf < 2; nf++)
#pragma unroll
                for (int h = 0; h < 2; h++)
#pragma unroll
                    for (int j = 0; j < 2; j++)
                        acc[nf][h * 2 + j] = esq_t[nn * 16 + nf * 8 + (lane & 3) * 2 + j];

#pragma unroll
            for (int ks = 0; ks < 16; ks++) {
                uint32_t ah[4], al[4], bh[4], bl[4];
                ldmx4(ah, sb + R_AH + aRow + (((uint32_t)(ks * 32) + aK) ^ aSw));
                ldmx4(al, sb + R_AL + aRow + (((uint32_t)(ks * 32) + aK) ^ aSw));
                ldmx4(bh, bufHi + bRow + (((uint32_t)(ks * 32) + bK) ^ aSw));
                ldmx4(bl, bufLo + bRow + (((uint32_t)(ks * 32) + bK) ^ aSw));
                mma16816(acc[0], ah, bh[0], bh[1]);
                mma16816(acc[1], ah, bh[2], bh[3]);
                mma16816(acc[0], ah, bl[0], bl[1]);
                mma16816(acc[1], ah, bl[2], bl[3]);
                mma16816(acc[0], al, bh[0], bh[1]);
                mma16816(acc[1], al, bh[2], bh[3]);
            }

#pragma unroll
            for (int h = 0; h < 2; h++) {
                float vmin = fminf(fminf(acc[0][h * 2], acc[0][h * 2 + 1]),
                                   fminf(acc[1][h * 2], acc[1][h * 2 + 1]));
                if (vmin < secv[h]) {
#pragma unroll
                    for (int nf = 0; nf < 2; nf++)
#pragma unroll
                        for (int j = 0; j < 2; j++) {
                            float sc = acc[nf][h * 2 + j];
                            int idx = code0 + t * 64 + nn * 16 + nf * 8 + (lane & 3) * 2 + j;
                            if (sc < bestv[h]) {
                                secv[h] = bestv[h]; bestv[h] = sc; besti[h] = idx;
                            } else if (sc < secv[h]) {
                                secv[h] = sc;
                            }
                        }
                }
            }
            __syncthreads();
        }

#pragma unroll
        for (int s = 0; s < 2; s++) {
#pragma unroll
            for (int off = 1; off < 4; off <<= 1) {
                float ob = __shfl_xor_sync(0xffffffffu, bestv[s], off);
                float os = __shfl_xor_sync(0xffffffffu, secv[s], off);
                int   oi = __shfl_xor_sync(0xffffffffu, besti[s], off);
                merge3(bestv[s], secv[s], besti[s], ob, os, oi);
            }
        }
        float* bR = reinterpret_cast<float*>(sm + R_RED);
        float* sR = bR + 128;
        int*   iR = reinterpret_cast<int*>(bR + 256);
        if ((lane & 3) == 0) {
#pragma unroll
            for (int s = 0; s < 2; s++) {
                int r = mm * 16 + (lane >> 2) + s * 8;
                bR[nn * 32 + r] = bestv[s];
                sR[nn * 32 + r] = secv[s];
                iR[nn * 32 + r] = besti[s];
            }
        }
        __syncthreads();
        if (tid < 32) {
            float b = bR[tid], s = sR[tid];
            int   i = iR[tid];
#pragma unroll
            for (int g2 = 1; g2 < 4; g2++)
                merge3(b, s, i, bR[g2 * 32 + tid], sR[g2 * 32 + tid], iR[g2 * 32 + tid]);
            int slot = base + tid;
            if (slot < count) {
                g_rb[slot * 8 + blockIdx.y] = b;
                g_rs[slot * 8 + blockIdx.y] = s;
                g_ri[slot * 8 + blockIdx.y] = i;
            }
        }
        __syncthreads();
    }
}

// merge 8 slices per risky slot
__global__ __launch_bounds__(256) void vq_merge() {
    int count = g_nrisky; if (count > RCAP) count = RCAP;
    int slot = blockIdx.x * 256 + threadIdx.x;
    if (slot >= count) return;
    float b = g_rb[slot * 8], s = g_rs[slot * 8];
    int   i = g_ri[slot * 8];
#pragma unroll
    for (int sl = 1; sl < 8; sl++)
        merge3(b, s, i, g_rb[slot * 8 + sl], g_rs[slot * 8 + sl], g_ri[slot * 8 + sl]);
    int row = g_risky[slot];
    g_row_idx[row] = i;
    if (s - b < TH2) {
        int p = atomicAdd(&g_nr2, 1);
        if (p < R2CAP) g_r2[p] = row;
    }
}

// ============================================================================
// Exact fp32 tail for near-tie rows
// ============================================================================
__global__ __launch_bounds__(256) void vq_exact(const float* __restrict__ z_e,
                                                const float* __restrict__ cb) {
    __shared__ float zs[DDIM];
    __shared__ float rv[256];
    __shared__ int   ri[256];
    const int tid = threadIdx.x;
    int n = g_nr2; if (n > R2CAP) n = R2CAP;
    for (int i = blockIdx.x; i < n; i += gridDim.x) {
        const int row = g_r2[i];
        zs[tid] = z_e[(size_t)row * DDIM + tid];
        __syncthreads();
        float bv = 3.4e38f; int bi = 0x7fffffff;
        const float4* z4 = reinterpret_cast<const float4*>(zs);
        for (int k = tid; k < KROWS; k += 256) {
            const float4* c4 = reinterpret_cast<const float4*>(cb + (size_t)k * DDIM);
            float dot = 0.f;
#pragma unroll
            for (int d = 0; d < DDIM / 4; d++) {
                float4 a = z4[d], e = c4[d];
                dot = fmaf(a.x, e.x, dot); dot = fmaf(a.y, e.y, dot);
                dot = fmaf(a.z, e.z, dot); dot = fmaf(a.w, e.w, dot);
            }
            float s = g_esq[k] - dot;
            if (s < bv || (s == bv && k < bi)) { bv = s; bi = k; }
        }
        rv[tid] = bv; ri[tid] = bi;
        __syncthreads();
#pragma unroll
        for (int st = 128; st > 0; st >>= 1) {
            if (tid < st) {
                float v2 = rv[tid + st]; int i2 = ri[tid + st];
                if (v2 < rv[tid] || (v2 == rv[tid] && i2 < ri[tid])) {
                    rv[tid] = v2; ri[tid] = i2;
                }
            }
            __syncthreads();
        }
        if (tid == 0) g_row_idx[row] = ri[0];
        __syncthreads();
    }
}

// ============================================================================
// Output epilogue (float4 lanes) + parallel final loss
// ============================================================================
__global__ __launch_bounds__(256)
void out_kernel(const float* __restrict__ z_e, const float* __restrict__ cb,
                float* __restrict__ out, long long out_size) {
    __shared__ float red[256];
    const int tid = threadIdx.x;
    const int row0 = blockIdx.x * 64;
    const int rsub = tid >> 6;
    const int c4   = tid & 63;
    float lsum = 0.f;
#pragma unroll 4
    for (int r = rsub; r < 64; r += 4) {
        const int row = row0 + r;
        const int idx = g_row_idx[row];
        float4 ze = reinterpret_cast<const float4*>(z_e + (size_t)row * DDIM)[c4];
        float4 zq = reinterpret_cast<const float4*>(cb + (size_t)idx * DDIM)[c4];
        float4 d;
        d.x = zq.x - ze.x; d.y = zq.y - ze.y; d.z = zq.z - ze.z; d.w = zq.w - ze.w;
        float4 o;
        o.x = ze.x + d.x; o.y = ze.y + d.y; o.z = ze.z + d.z; o.w = ze.w + d.w;
        long long pos = (long long)row * DDIM + c4 * 4;
        if (pos + 3 < out_size)
            reinterpret_cast<float4*>(out)[pos >> 2] = o;
        lsum += d.x * d.x + d.y * d.y + d.z * d.z + d.w * d.w;
    }
    if (tid < 64) {
        long long pos = (long long)BROWS * DDIM + row0 + tid;
        if (pos < out_size) out[pos] = (float)g_row_idx[row0 + tid];
    }
    red[tid] = lsum;
    __syncthreads();
#pragma unroll
    for (int st = 128; st > 0; st >>= 1) {
        if (tid < st) red[tid] += red[tid + st];
        __syncthreads();
    }
    if (tid == 0) g_partial[blockIdx.x] = red[0];
}

__global__ __launch_bounds__(512) void final_kernel(float* __restrict__ out,
                                                    long long out_size) {
    __shared__ float red[512];
    const int tid = threadIdx.x;
    red[tid] = g_partial[tid];
    __syncthreads();
#pragma unroll
    for (int st = 256; st > 0; st >>= 1) {
        if (tid < st) red[tid] += red[tid + st];
        __syncthreads();
    }
    if (tid == 0) {
        float mse = red[0] / ((float)BROWS * (float)DDIM);
        long long pos = (long long)BROWS * DDIM + BROWS;
        if (pos < out_size) out[pos] = 1.25f * mse;
    }
}

// ============================================================================
extern "C" void kernel_launch(void* const* d_in, const int* in_sizes, int n_in,
                              void* d_out, int out_size) {
    const float* z_e = (const float*)d_in[0];
    const float* cb  = (const float*)d_in[1];
    float* out       = (float*)d_out;

    void *p_zhi, *p_zlo, *p_chi, *p_clo;
    cudaGetSymbolAddress(&p_zhi, g_z_hi);
    cudaGetSymbolAddress(&p_zlo, g_z_lo);
    cudaGetSymbolAddress(&p_chi, g_cb_hi);
    cudaGetSymbolAddress(&p_clo, g_cb_lo);

    split_kernel<<<(BROWS * DDIM / 4) / 256, 256>>>(
        z_e, (__half*)p_zhi, (__half*)p_zlo, BROWS * DDIM / 4, -1.0f);
    split_kernel<<<(KROWS * DDIM / 4) / 256, 256>>>(
        cb, (__half*)p_chi, (__half*)p_clo, KROWS * DDIM / 4, 1.0f);
    esq_kernel<<<KROWS / 8, 256>>>(cb);

    cudaFuncSetAttribute(vq_screen, cudaFuncAttributeMaxDynamicSharedMemorySize,
                         SCR_SMEM);
    vq_screen<<<BROWS / 64, 256, SCR_SMEM>>>();

    cudaFuncSetAttribute(vq_rescue, cudaFuncAttributeMaxDynamicSharedMemorySize,
                         RES_SMEM);
    dim3 rg(32, 8);
    vq_rescue<<<rg, 256, RES_SMEM>>>();
    vq_merge<<<RCAP / 256, 256>>>();

    vq_exact<<<128, 256>>>(z_e, cb);
    out_kernel<<<BROWS / 64, 256>>>(z_e, cb, out, (long long)out_size);
    final_kernel<<<1, 512>>>(out, (long long)out_size);
}